// round 3
// baseline (speedup 1.0000x reference)
#include <cuda_runtime.h>
#include <math.h>

// Problem constants
#define BB 64
#define TT 512
#define II 1024
#define HH 1024

#define NB_CTAS 128   // recurrent kernel grid (32 H-tiles x 4 B-tiles)
#define RNN_THREADS 256

// ---------------- device scratch (static allocation only) ----------------
__device__ float g_h[2][BB * HH];     // ping-pong hidden state
__device__ unsigned int g_bar;        // grid barrier counter

// ---------------- init: copy h0, reset barrier ----------------
__global__ void init_kernel(const float* __restrict__ h0) {
    int i = blockIdx.x * blockDim.x + threadIdx.x;
    if (i < BB * HH) g_h[0][i] = h0[i];
    if (i == 0) g_bar = 0u;
}

// ---------------- phase 1: xp = x @ W_ih^T + b_ih  ->  d_out -------------
// C[m][n] = sum_k A[m][k] * Bm[n][k] + bias[n]
// M = B*T = 32768, N = 1024, K = 1024. Tile 64x64x16, 256 threads, 4x4/thread.
__global__ void __launch_bounds__(256) gemm_xw_kernel(
    const float* __restrict__ A,    // x  [M][K]
    const float* __restrict__ Bm,   // W_ih [N][K]
    const float* __restrict__ bias, // b_ih [N]
    float* __restrict__ C)          // out [M][N]
{
    __shared__ float As[16][68];
    __shared__ float Bs[16][68];

    const int tid = threadIdx.x;
    const int n0 = blockIdx.x * 64;
    const int m0 = blockIdx.y * 64;

    const int row = tid >> 2;     // 0..63
    const int kq  = tid & 3;      // 0..3 (float4 within k-tile)
    const int tx  = tid & 15;     // n dim thread
    const int ty  = tid >> 4;     // m dim thread

    float acc[4][4] = {};

    const float* aptr = A  + (size_t)(m0 + row) * II + kq * 4;
    const float* bptr = Bm + (size_t)(n0 + row) * II + kq * 4;

    for (int kt = 0; kt < II; kt += 16) {
        float4 va = *(const float4*)(aptr + kt);
        float4 vb = *(const float4*)(bptr + kt);
        __syncthreads();
        As[kq * 4 + 0][row] = va.x;
        As[kq * 4 + 1][row] = va.y;
        As[kq * 4 + 2][row] = va.z;
        As[kq * 4 + 3][row] = va.w;
        Bs[kq * 4 + 0][row] = vb.x;
        Bs[kq * 4 + 1][row] = vb.y;
        Bs[kq * 4 + 2][row] = vb.z;
        Bs[kq * 4 + 3][row] = vb.w;
        __syncthreads();
#pragma unroll
        for (int k = 0; k < 16; k++) {
            float4 a = *(const float4*)(&As[k][ty * 4]);
            float4 b = *(const float4*)(&Bs[k][tx * 4]);
            acc[0][0] += a.x * b.x; acc[0][1] += a.x * b.y; acc[0][2] += a.x * b.z; acc[0][3] += a.x * b.w;
            acc[1][0] += a.y * b.x; acc[1][1] += a.y * b.y; acc[1][2] += a.y * b.z; acc[1][3] += a.y * b.w;
            acc[2][0] += a.z * b.x; acc[2][1] += a.z * b.y; acc[2][2] += a.z * b.z; acc[2][3] += a.z * b.w;
            acc[3][0] += a.w * b.x; acc[3][1] += a.w * b.y; acc[3][2] += a.w * b.z; acc[3][3] += a.w * b.w;
        }
    }

    float4 b4 = *(const float4*)(bias + n0 + tx * 4);
#pragma unroll
    for (int i = 0; i < 4; i++) {
        float4 o;
        o.x = acc[i][0] + b4.x;
        o.y = acc[i][1] + b4.y;
        o.z = acc[i][2] + b4.z;
        o.w = acc[i][3] + b4.w;
        *(float4*)(C + (size_t)(m0 + ty * 4 + i) * HH + n0 + tx * 4) = o;
    }
}

// ---------------- phase 2: persistent recurrent scan ---------------------
// Grid = 128 CTAs = 32 H-tiles (32 cols) x 4 B-tiles (16 rows), 256 threads.
// W_hh slice stays resident in smem (k-major [1024][32]) for all 512 steps.
// 8-way split-K: warp w handles k in [w*128, w*128+128). Per-thread 4x4 tile.
__global__ void __launch_bounds__(RNN_THREADS, 1) rnn_scan_kernel(
    const float* __restrict__ W_hh,  // [H][H]
    const float* __restrict__ b_hh,  // [H]
    float* __restrict__ out)         // [B][T][H], holds xp pre-activations on entry
{
    extern __shared__ float sm[];
    float* Ws  = sm;                       // 1024*32 = 32768 floats (k-major)
    float* Hs  = sm + 32768;               // 16 rows * 1025 = 16400 floats
    float* red = sm + 32768 + 16400;       // 512 outputs * stride 9 = 4608 floats

    const int tid  = threadIdx.x;
    const int bid  = blockIdx.x;
    const int ht   = bid & 31;   // H tile 0..31
    const int bt   = bid >> 5;   // B tile 0..3
    const int warp = tid >> 5;   // k-slice 0..7
    const int lane = tid & 31;
    const int tb   = lane >> 3;  // 0..3 -> 4 b rows
    const int tc   = lane & 7;   // 0..7 -> 4 c cols

    // ---- load W_hh slice into smem, k-major ----
    for (int idx = tid; idx < 32 * 256; idx += RNN_THREADS) {
        int c  = idx >> 8;      // 0..31 local col
        int k4 = idx & 255;     // float4 along k
        float4 v = *(const float4*)(W_hh + (size_t)(ht * 32 + c) * HH + k4 * 4);
        Ws[(k4 * 4 + 0) * 32 + c] = v.x;
        Ws[(k4 * 4 + 1) * 32 + c] = v.y;
        Ws[(k4 * 4 + 2) * 32 + c] = v.z;
        Ws[(k4 * 4 + 3) * 32 + c] = v.w;
    }

    // ---- epilogue constants (each thread finalizes 2 adjacent outputs) ----
    const int o0  = tid * 2;              // even, o1 = o0+1 same b row
    const int b0l = o0 >> 5;
    const int c0l = o0 & 31;
    const int gb  = bt * 16 + b0l;
    const int gc  = ht * 32 + c0l;
    const float bh0 = b_hh[gc];
    const float bh1 = b_hh[gc + 1];

    const int k0 = warp * 128;

    for (int t = 0; t < TT; ++t) {
        const int cur = t & 1;
        const int nxt = cur ^ 1;
        const float* hsrc = &g_h[cur][0];

        __syncthreads();
        // ---- load h_{t-1} tile (bypass L1: written by other SMs) ----
        for (int idx = tid; idx < 16 * 256; idx += RNN_THREADS) {
            int b  = idx >> 8;
            int k4 = idx & 255;
            float4 v = __ldcg((const float4*)(hsrc + (size_t)(bt * 16 + b) * HH + k4 * 4));
            int base = b * 1025 + k4 * 4;
            Hs[base + 0] = v.x;
            Hs[base + 1] = v.y;
            Hs[base + 2] = v.z;
            Hs[base + 3] = v.w;
        }
        __syncthreads();

        // ---- partial GEMM: acc[4][4] over this warp's k-slice ----
        float acc[4][4] = {};
        const float* wp = Ws + tc * 4;
#pragma unroll 4
        for (int k = k0; k < k0 + 128; ++k) {
            float4 w4 = *(const float4*)(wp + k * 32);
#pragma unroll
            for (int i = 0; i < 4; i++) {
                float hv = Hs[(tb * 4 + i) * 1025 + k];
                acc[i][0] += hv * w4.x;
                acc[i][1] += hv * w4.y;
                acc[i][2] += hv * w4.z;
                acc[i][3] += hv * w4.w;
            }
        }

        // ---- cross-warp reduction via smem (stride 9 to dodge bank conflicts) ----
#pragma unroll
        for (int i = 0; i < 4; i++) {
#pragma unroll
            for (int j = 0; j < 4; j++) {
                int o = (tb * 4 + i) * 32 + tc * 4 + j;
                red[o * 9 + warp] = acc[i][j];
            }
        }
        __syncthreads();

        float s0 = 0.f, s1 = 0.f;
#pragma unroll
        for (int s = 0; s < 8; s++) {
            s0 += red[o0 * 9 + s];
            s1 += red[(o0 + 1) * 9 + s];
        }

        const size_t outIdx = ((size_t)gb * TT + t) * HH + gc;
        float pre0 = s0 + out[outIdx]     + bh0;
        float pre1 = s1 + out[outIdx + 1] + bh1;
        float h0v = tanhf(pre0);
        float h1v = tanhf(pre1);
        out[outIdx]     = h0v;
        out[outIdx + 1] = h1v;
        __stcg(&g_h[nxt][(size_t)gb * HH + gc],     h0v);
        __stcg(&g_h[nxt][(size_t)gb * HH + gc + 1], h1v);

        // ---- grid barrier (all 128 CTAs resident: occ=1, grid < #SMs) ----
        __threadfence();
        __syncthreads();
        if (tid == 0) {
            atomicAdd(&g_bar, 1u);
            const unsigned int target = (unsigned int)(NB_CTAS * (t + 1));
            while (*((volatile unsigned int*)&g_bar) < target) { }
        }
        __syncthreads();
    }
}

// ---------------- launch ----------------
extern "C" void kernel_launch(void* const* d_in, const int* in_sizes, int n_in,
                              void* d_out, int out_size) {
    const float* x    = (const float*)d_in[0];
    const float* h0   = (const float*)d_in[1];
    const float* W_ih = (const float*)d_in[2];
    const float* b_ih = (const float*)d_in[3];
    const float* W_hh = (const float*)d_in[4];
    const float* b_hh = (const float*)d_in[5];
    float* out = (float*)d_out;

    // init hidden state + barrier
    init_kernel<<<(BB * HH + 255) / 256, 256>>>(h0);

    // phase 1: xp into d_out
    dim3 g1(HH / 64, (BB * TT) / 64);
    gemm_xw_kernel<<<g1, 256>>>(x, W_ih, b_ih, out);

    // phase 2: persistent recurrent scan
    const int smem_bytes = (32768 + 16400 + 4608) * sizeof(float); // 215104 B
    cudaFuncSetAttribute(rnn_scan_kernel,
                         cudaFuncAttributeMaxDynamicSharedMemorySize, smem_bytes);
    rnn_scan_kernel<<<NB_CTAS, RNN_THREADS, smem_bytes>>>(W_hh, b_hh, out);
}

// round 5
// speedup vs baseline: 1.9511x; 1.9511x over previous
#include <cuda_runtime.h>
#include <math.h>

// Problem constants
#define BB 64
#define TT 512
#define II 1024
#define HH 1024

#define NB_CTAS 128
#define RNN_THREADS 256

// ---------------- device scratch ----------------
__device__ float g_h[2][BB * HH];     // ping-pong hidden state
__device__ unsigned int g_bar;        // grid barrier counter

// ---------------- helpers ----------------
__device__ __forceinline__ unsigned f2tf32(float x) {
    unsigned r;
    asm("cvt.rna.tf32.f32 %0, %1;" : "=r"(r) : "f"(x));
    return r;
}

__device__ __forceinline__ void ldmat_x4(unsigned* r, unsigned addr) {
    asm volatile("ldmatrix.sync.aligned.m8n8.x4.shared.b16 {%0,%1,%2,%3}, [%4];"
                 : "=r"(r[0]), "=r"(r[1]), "=r"(r[2]), "=r"(r[3]) : "r"(addr));
}

__device__ __forceinline__ void mma_tf32(float* c, const unsigned* a, unsigned b0, unsigned b1) {
    asm volatile(
        "mma.sync.aligned.m16n8k8.row.col.f32.tf32.tf32.f32 "
        "{%0,%1,%2,%3},{%4,%5,%6,%7},{%8,%9},{%0,%1,%2,%3};"
        : "+f"(c[0]), "+f"(c[1]), "+f"(c[2]), "+f"(c[3])
        : "r"(a[0]), "r"(a[1]), "r"(a[2]), "r"(a[3]), "r"(b0), "r"(b1));
}

// ---------------- init ----------------
__global__ void init_kernel(const float* __restrict__ h0) {
    int i = blockIdx.x * blockDim.x + threadIdx.x;
    if (i < BB * HH) g_h[0][i] = h0[i];
    if (i == 0) g_bar = 0u;
}

// ---------------- phase 1: xp = x @ W_ih^T + b_ih  (tf32 mma) -------------
// CTA tile 128(M) x 128(N), k-chunk 32. 8 warps (2m x 4n), warp tile 64x32.
__global__ void __launch_bounds__(256) gemm_xw_mma(
    const float* __restrict__ A,    // x [M][K]
    const float* __restrict__ W,    // W_ih [N][K]
    const float* __restrict__ bias, // [N]
    float* __restrict__ C)          // [M][N]
{
    __shared__ unsigned As[128 * 32];
    __shared__ unsigned Ws[128 * 32];

    const int tid  = threadIdx.x;
    const int lane = tid & 31;
    const int warp = tid >> 5;
    const int wm   = warp & 1;   // 0..1
    const int wn   = warp >> 1;  // 0..3
    const int n0   = blockIdx.x * 128;
    const int m0   = blockIdx.y * 128;

    const unsigned AsB = (unsigned)__cvta_generic_to_shared(As);
    const unsigned WsB = (unsigned)__cvta_generic_to_shared(Ws);

    float c[4][4][4] = {};

    // granule assignment for loads: 1024 granules per tile, 4 per thread
    int lr[4], lg[4];
    size_t aoff[4], woff[4];
#pragma unroll
    for (int i = 0; i < 4; i++) {
        int idx = tid + i * 256;
        lr[i] = idx >> 3;
        lg[i] = idx & 7;
        aoff[i] = (size_t)(m0 + lr[i]) * II + lg[i] * 4;
        woff[i] = (size_t)(n0 + lr[i]) * II + lg[i] * 4;
    }

    float4 ra[4], rw[4];
#pragma unroll
    for (int i = 0; i < 4; i++) {
        ra[i] = *(const float4*)(A + aoff[i]);
        rw[i] = *(const float4*)(W + woff[i]);
    }

    for (int kc = 0; kc < 32; kc++) {
        __syncthreads();
#pragma unroll
        for (int i = 0; i < 4; i++) {
            uint4 ua = { f2tf32(ra[i].x), f2tf32(ra[i].y), f2tf32(ra[i].z), f2tf32(ra[i].w) };
            uint4 uw = { f2tf32(rw[i].x), f2tf32(rw[i].y), f2tf32(rw[i].z), f2tf32(rw[i].w) };
            int off = lr[i] * 32 + ((lg[i] ^ (lr[i] & 7)) << 2);
            *(uint4*)&As[off] = ua;
            *(uint4*)&Ws[off] = uw;
        }
        __syncthreads();

        if (kc + 1 < 32) {
            int k0 = (kc + 1) * 32;
#pragma unroll
            for (int i = 0; i < 4; i++) {
                ra[i] = *(const float4*)(A + aoff[i] + k0);
                rw[i] = *(const float4*)(W + woff[i] + k0);
            }
        }

#pragma unroll
        for (int ks = 0; ks < 4; ks++) {
            unsigned a[4][4], b[4][2];
#pragma unroll
            for (int mi = 0; mi < 4; mi++) {
                int r = wm * 64 + mi * 16 + ((lane >> 3) & 1) * 8 + (lane & 7);
                int g = ks * 2 + (lane >> 4);
                ldmat_x4(a[mi], AsB + (unsigned)(r * 32 + ((g ^ (r & 7)) << 2)) * 4u);
            }
#pragma unroll
            for (int p = 0; p < 2; p++) {
                int r = wn * 32 + p * 16 + (lane >> 4) * 8 + (lane & 7);
                int g = ks * 2 + ((lane >> 3) & 1);
                unsigned t[4];
                ldmat_x4(t, WsB + (unsigned)(r * 32 + ((g ^ (r & 7)) << 2)) * 4u);
                b[p * 2 + 0][0] = t[0]; b[p * 2 + 0][1] = t[1];
                b[p * 2 + 1][0] = t[2]; b[p * 2 + 1][1] = t[3];
            }
#pragma unroll
            for (int mi = 0; mi < 4; mi++)
#pragma unroll
                for (int ni = 0; ni < 4; ni++)
                    mma_tf32(c[mi][ni], a[mi], b[ni][0], b[ni][1]);
        }
    }

    // epilogue: add bias, store
#pragma unroll
    for (int mi = 0; mi < 4; mi++) {
        int r = m0 + wm * 64 + mi * 16 + (lane >> 2);
#pragma unroll
        for (int ni = 0; ni < 4; ni++) {
            int col = n0 + wn * 32 + ni * 8 + (lane & 3) * 2;
            float2 bv = *(const float2*)&bias[col];
            float2 o0 = { c[mi][ni][0] + bv.x, c[mi][ni][1] + bv.y };
            float2 o1 = { c[mi][ni][2] + bv.x, c[mi][ni][3] + bv.y };
            *(float2*)&C[(size_t)r * HH + col]       = o0;
            *(float2*)&C[(size_t)(r + 8) * HH + col] = o1;
        }
    }
}

// ---------------- phase 2: persistent recurrent scan (tf32 mma) ----------
// 128 CTAs = 32 H-tiles (32 cols) x 4 B-tiles (16 rows). W_hh slice resident
// in smem, n-major tf32 swizzled. 8 warps = 2 n-halves x 4-way split-K.
__global__ void __launch_bounds__(RNN_THREADS, 1) rnn_scan_mma(
    const float* __restrict__ W_hh,
    const float* __restrict__ b_hh,
    float* __restrict__ out)
{
    extern __shared__ unsigned smbuf[];
    unsigned* Wt = smbuf;             // [32][1024] tf32 swizzled (n-major)
    unsigned* Ht = smbuf + 32 * 1024; // [16][1024] tf32 swizzled
    float* red = (float*)(smbuf + 48 * 1024); // [48][36]

    const int tid  = threadIdx.x;
    const int lane = tid & 31;
    const int warp = tid >> 5;
    const int nf2  = warp & 1;   // n half: cols 0-15 / 16-31
    const int kq   = warp >> 1;  // k quarter: 256 k each
    const int bid  = blockIdx.x;
    const int ht   = bid & 31;
    const int bt   = bid >> 5;

    const unsigned HtB = (unsigned)__cvta_generic_to_shared(Ht);
    const unsigned WtB = (unsigned)__cvta_generic_to_shared(Wt);

    // ---- load W_hh slice: 32 rows x 256 granules ----
#pragma unroll
    for (int i = 0; i < 32; i++) {
        int idx = tid + i * 256;
        int r = idx >> 8, g = idx & 255;
        float4 v = *(const float4*)(W_hh + (((size_t)(ht * 32 + r)) << 10) + g * 4);
        uint4 u = { f2tf32(v.x), f2tf32(v.y), f2tf32(v.z), f2tf32(v.w) };
        *(uint4*)&Wt[r * 1024 + ((g ^ (r & 7)) << 2)] = u;
    }

    // ---- epilogue constants (warps 0-1 only) ----
    const int r0 = lane >> 2;                        // 0..7
    const int cb = nf2 * 16 + 2 * (lane & 3);        // col base within tile
    float2 bh[2];
    if (kq == 0) {
        bh[0] = *(const float2*)&b_hh[ht * 32 + cb];
        bh[1] = *(const float2*)&b_hh[ht * 32 + cb + 8];
    }

    const int kg0 = kq << 6;  // granule base of this warp's k quarter

    for (int t = 0; t < TT; ++t) {
        const int cur = t & 1;
        const int nxt = cur ^ 1;
        const float* hsrc = &g_h[cur][0];

        // ---- load h_{t-1} tile (L2, written by other SMs) ----
#pragma unroll
        for (int i = 0; i < 16; i++) {
            int idx = tid + i * 256;
            int r = idx >> 8, g = idx & 255;
            float4 v = __ldcg((const float4*)(hsrc + (((size_t)(bt * 16 + r)) << 10) + g * 4));
            uint4 u = { f2tf32(v.x), f2tf32(v.y), f2tf32(v.z), f2tf32(v.w) };
            *(uint4*)&Ht[r * 1024 + ((g ^ (r & 7)) << 2)] = u;
        }
        __syncthreads();

        // ---- mma over this warp's 256-k quarter, 2 n-frags ----
        float c[2][2][4] = {};  // [k-step parity copy][n-frag][frag]
#pragma unroll 4
        for (int s2 = 0; s2 < 16; s2++) {
            int g0 = kg0 + s2 * 4;
            unsigned a0[4], a1[4], b0[4], b1[4];
            {
                int r = (lane & 7) + ((lane >> 3) & 1) * 8;
                int g = g0 + (lane >> 4);
                ldmat_x4(a0, HtB + (unsigned)(r * 1024 + ((g ^ (r & 7)) << 2)) * 4u);
                g += 2;
                ldmat_x4(a1, HtB + (unsigned)(r * 1024 + ((g ^ (r & 7)) << 2)) * 4u);
            }
            {
                int r = nf2 * 16 + (lane & 7);
                int g = g0 + (lane >> 3);
                ldmat_x4(b0, WtB + (unsigned)(r * 1024 + ((g ^ (r & 7)) << 2)) * 4u);
                int r2 = r + 8;
                ldmat_x4(b1, WtB + (unsigned)(r2 * 1024 + ((g ^ (r2 & 7)) << 2)) * 4u);
            }
            mma_tf32(c[0][0], a0, b0[0], b0[1]);
            mma_tf32(c[0][1], a0, b1[0], b1[1]);
            mma_tf32(c[1][0], a1, b0[2], b0[3]);
            mma_tf32(c[1][1], a1, b1[2], b1[3]);
        }

        float cc[2][4];
#pragma unroll
        for (int ni = 0; ni < 2; ni++)
#pragma unroll
            for (int j = 0; j < 4; j++)
                cc[ni][j] = c[0][ni][j] + c[1][ni][j];

        // ---- split-K reduction: warps with kq>0 write, kq==0 reads ----
        if (kq != 0) {
#pragma unroll
            for (int ni = 0; ni < 2; ni++) {
#pragma unroll
                for (int half = 0; half < 2; half++) {
                    int rr = (kq - 1) * 16 + r0 + 8 * half;
                    int colw = cb + ni * 8;
                    red[rr * 36 + colw]     = cc[ni][half * 2];
                    red[rr * 36 + colw + 1] = cc[ni][half * 2 + 1];
                }
            }
        }
        __syncthreads();

        if (kq == 0) {
#pragma unroll
            for (int s = 0; s < 3; s++)
#pragma unroll
                for (int ni = 0; ni < 2; ni++)
#pragma unroll
                    for (int half = 0; half < 2; half++) {
                        int rr = s * 16 + r0 + 8 * half;
                        int colw = cb + ni * 8;
                        cc[ni][half * 2]     += red[rr * 36 + colw];
                        cc[ni][half * 2 + 1] += red[rr * 36 + colw + 1];
                    }

            // ---- epilogue: pre = cc + xp + b_hh; h = tanh(pre) ----
#pragma unroll
            for (int ni = 0; ni < 2; ni++) {
#pragma unroll
                for (int half = 0; half < 2; half++) {
                    int gb = bt * 16 + r0 + 8 * half;
                    int gc = ht * 32 + cb + ni * 8;
                    size_t oIdx = ((size_t)gb * TT + t) * HH + gc;
                    float2 xp = *(const float2*)(out + oIdx);
                    float p0 = cc[ni][half * 2]     + xp.x + bh[ni].x;
                    float p1 = cc[ni][half * 2 + 1] + xp.y + bh[ni].y;
                    float2 hv = { tanhf(p0), tanhf(p1) };
                    *(float2*)(out + oIdx) = hv;
                    __stcg((float2*)&g_h[nxt][(size_t)gb * HH + gc], hv);
                }
            }
        }

        // ---- grid barrier ----
        __threadfence();
        __syncthreads();
        if (tid == 0) {
            atomicAdd(&g_bar, 1u);
            const unsigned target = (unsigned)(NB_CTAS * (t + 1));
            while (*((volatile unsigned*)&g_bar) < target) { }
        }
        __syncthreads();
    }
}

// ---------------- launch ----------------
extern "C" void kernel_launch(void* const* d_in, const int* in_sizes, int n_in,
                              void* d_out, int out_size) {
    const float* x    = (const float*)d_in[0];
    const float* h0   = (const float*)d_in[1];
    const float* W_ih = (const float*)d_in[2];
    const float* b_ih = (const float*)d_in[3];
    const float* W_hh = (const float*)d_in[4];
    const float* b_hh = (const float*)d_in[5];
    float* out = (float*)d_out;

    init_kernel<<<(BB * HH + 255) / 256, 256>>>(h0);

    dim3 g1(HH / 128, (BB * TT) / 128);
    gemm_xw_mma<<<g1, 256>>>(x, W_ih, b_ih, out);

    const int smem_bytes = (48 * 1024) * 4 + 48 * 36 * 4;  // 203520 B
    cudaFuncSetAttribute(rnn_scan_mma,
                         cudaFuncAttributeMaxDynamicSharedMemorySize, smem_bytes);
    rnn_scan_mma<<<NB_CTAS, RNN_THREADS, smem_bytes>>>(W_hh, b_hh, out);
}